// round 4
// baseline (speedup 1.0000x reference)
#include <cuda_runtime.h>

// TopKGate: S=8192 tokens, D=2048 model dim, E=64 experts, top-1, capacity=128.
// Outputs (reference tuple, assumed concatenated as float32):
//   l_aux [1], combine_weights [S,E,C], dispatch_mask [S,E,C] (bool->1.0), exp_counts [E]

#define S 8192
#define DD 2048
#define E 64
#define CAP 128

typedef unsigned int u32;
typedef unsigned long long u64;

// ---------------- scratch (device globals; no runtime allocation) ----------------
__device__ int   g_tok_e[S];      // argmax expert per token
__device__ float g_tok_g[S];      // winner gate value (= 1/sumexp)
__device__ float g_tok_noise[S];  // jax uniform noise at (s, e_s)
__device__ float g_gsum[E];       // column sums of gates (for l_aux)
__device__ int   g_cnt[E];        // expert counts (pre-capacity)

// ---------------- packed f32x2 FMA (ptxas never emits FFMA2 from C++) ----------------
__device__ __forceinline__ u64 ffma2(u64 a, u64 b, u64 c) {
    u64 d;
    asm("fma.rn.f32x2 %0, %1, %2, %3;" : "=l"(d) : "l"(a), "l"(b), "l"(c));
    return d;
}
__device__ __forceinline__ u64 pack2(float x, float y) {
    u64 d;
    asm("mov.b64 %0, {%1, %2};" : "=l"(d) : "f"(x), "f"(y));
    return d;
}
__device__ __forceinline__ float2 unpack2(u64 a) {
    float x, y;
    asm("mov.b64 {%0, %1}, %2;" : "=f"(x), "=f"(y) : "l"(a));
    return make_float2(x, y);
}

// ---------------- JAX threefry2x32, partitionable path (default since jax 0.4.36) ----
// per element i: counter (hi, lo) = (i >> 32, i & 0xffffffff) = (0, i) here.
// 32-bit random bits = y0 ^ y1. uniform = bitcast((bits>>9)|0x3f800000) - 1, clamped >= 0.
__device__ __forceinline__ u32 rotl32(u32 x, int r) { return (x << r) | (x >> (32 - r)); }

__device__ float jax_uniform_noise(u32 idx) {
    u32 x0 = 0u, x1 = idx;                 // (counts >> 32, counts & 0xffffffff)
    const u32 k0 = 0u, k1 = 42u, k2 = k0 ^ k1 ^ 0x1BD11BDAu;  // key(42) -> (0, 42)
    x0 += k0; x1 += k1;
#define RND(r) { x0 += x1; x1 = rotl32(x1, r); x1 ^= x0; }
    RND(13) RND(15) RND(26) RND(6)   x0 += k1; x1 += k2 + 1u;
    RND(17) RND(29) RND(16) RND(24)  x0 += k2; x1 += k0 + 2u;
    RND(13) RND(15) RND(26) RND(6)   x0 += k0; x1 += k1 + 3u;
    RND(17) RND(29) RND(16) RND(24)  x0 += k1; x1 += k2 + 4u;
    RND(13) RND(15) RND(26) RND(6)   x0 += k2; x1 += k0 + 5u;
#undef RND
    u32 bits = x0 ^ x1;                    // partitionable 32-bit output
    float u = __uint_as_float((bits >> 9) | 0x3f800000u) - 1.0f;
    return u < 0.f ? 0.f : u;
}

// ---------------- init scratch ----------------
__global__ void init_scratch() {
    int t = threadIdx.x;
    if (t < E) { g_gsum[t] = 0.f; g_cnt[t] = 0; }
}

// ---------------- zero-fill output ----------------
__global__ void zero_out_k(float* __restrict__ p, long long n) {
    long long i = (long long)blockIdx.x * blockDim.x + threadIdx.x;
    long long stride = (long long)gridDim.x * blockDim.x;
    long long n4 = n >> 2;
    float4 z = make_float4(0.f, 0.f, 0.f, 0.f);
    for (long long v = i; v < n4; v += stride) ((float4*)p)[v] = z;
    for (long long v = n4 * 4 + i; v < n; v += stride) p[v] = 0.f;
}

// ---------------- fused GEMM + softmax + argmax + noise + counters ----------------
// grid 128 CTAs (64 tokens each), 128 threads.
// thread (ty=tid/8, tx=tid%8): tokens t_i = ty + 16*i (i<4), experts e_j = tx + 8*j (j<8).
// smem tiles stride 68 floats -> conflict-free LDS.128 with these lane maps.
__global__ __launch_bounds__(128) void gate_gemm(const float* __restrict__ x,
                                                 const float* __restrict__ wg) {
    __shared__ float xs[64 * 68];
    __shared__ float ws[64 * 68];
    __shared__ float scol[E];
    __shared__ int scnt[E];

    int tid = threadIdx.x;
    int tok0 = blockIdx.x * 64;
    if (tid < E) { scol[tid] = 0.f; scnt[tid] = 0; }
    int ty = tid >> 3, tx = tid & 7;

    u64 acc[4][8];
#pragma unroll
    for (int i = 0; i < 4; i++)
#pragma unroll
        for (int jj = 0; jj < 8; jj++) acc[i][jj] = 0ull;

    const int NCHUNK = DD / 64;  // 32
    float4 sx[8], sw[8];
    // preload chunk 0 into registers
#pragma unroll
    for (int u = 0; u < 8; u++) {
        int v = tid + u * 128; int r = v >> 4, c4 = v & 15;
        sx[u] = *(const float4*)&x[(size_t)(tok0 + r) * DD + c4 * 4];
        sw[u] = *(const float4*)&wg[(size_t)r * DD + c4 * 4];
    }

    for (int c = 0; c < NCHUNK; c++) {
        // commit staged registers to smem
#pragma unroll
        for (int u = 0; u < 8; u++) {
            int v = tid + u * 128; int r = v >> 4, c4 = v & 15;
            *(float4*)&xs[r * 68 + c4 * 4] = sx[u];
            *(float4*)&ws[r * 68 + c4 * 4] = sw[u];
        }
        __syncthreads();
        // prefetch next chunk (latency hidden under compute)
        if (c + 1 < NCHUNK) {
            int k0 = (c + 1) * 64;
#pragma unroll
            for (int u = 0; u < 8; u++) {
                int v = tid + u * 128; int r = v >> 4, c4 = v & 15;
                sx[u] = *(const float4*)&x[(size_t)(tok0 + r) * DD + k0 + c4 * 4];
                sw[u] = *(const float4*)&wg[(size_t)r * DD + k0 + c4 * 4];
            }
        }
        // compute 64 k-steps on current chunk
#pragma unroll
        for (int kk = 0; kk < 64; kk += 4) {
            u64 xp0[4], xp1[4];
#pragma unroll
            for (int i = 0; i < 4; i++) {
                float4 xv = *(const float4*)&xs[(ty + 16 * i) * 68 + kk];
                xp0[i] = pack2(xv.x, xv.y);
                xp1[i] = pack2(xv.z, xv.w);
            }
#pragma unroll
            for (int jj = 0; jj < 8; jj++) {
                float4 wv = *(const float4*)&ws[(tx + 8 * jj) * 68 + kk];
                u64 w0 = pack2(wv.x, wv.y), w1 = pack2(wv.z, wv.w);
#pragma unroll
                for (int i = 0; i < 4; i++) {
                    acc[i][jj] = ffma2(xp0[i], w0, acc[i][jj]);
                    acc[i][jj] = ffma2(xp1[i], w1, acc[i][jj]);
                }
            }
        }
        __syncthreads();
    }

    // logits
    float vals[4][8];
#pragma unroll
    for (int i = 0; i < 4; i++)
#pragma unroll
        for (int jj = 0; jj < 8; jj++) {
            float2 f = unpack2(acc[i][jj]);
            vals[i][jj] = f.x + f.y;
        }

    // per-token softmax + argmax (reduce across 8 tx lanes)
#pragma unroll
    for (int i = 0; i < 4; i++) {
        int t = ty + 16 * i;
        float m = -1e30f; int be = 0;
#pragma unroll
        for (int jj = 0; jj < 8; jj++) {
            float v = vals[i][jj]; int e = tx + 8 * jj;
            if (v > m) { m = v; be = e; }
        }
#pragma unroll
        for (int o = 4; o >= 1; o >>= 1) {
            float mo = __shfl_xor_sync(0xffffffffu, m, o);
            int eo = __shfl_xor_sync(0xffffffffu, be, o);
            if (mo > m || (mo == m && eo < be)) { m = mo; be = eo; }  // jnp.argmax: first max
        }
        float ex[8];
        float lsum = 0.f;
#pragma unroll
        for (int jj = 0; jj < 8; jj++) { ex[jj] = expf(vals[i][jj] - m); lsum += ex[jj]; }
#pragma unroll
        for (int o = 4; o >= 1; o >>= 1) lsum += __shfl_xor_sync(0xffffffffu, lsum, o);
        float inv = 1.0f / lsum;
#pragma unroll
        for (int jj = 0; jj < 8; jj++) atomicAdd(&scol[tx + 8 * jj], ex[jj] * inv);
        if (tx == 0) {
            int s = tok0 + t;
            g_tok_e[s] = be;
            g_tok_g[s] = inv;  // winner gate = exp(0)/sumexp
            g_tok_noise[s] = jax_uniform_noise((u32)s * E + (u32)be);
            atomicAdd(&scnt[be], 1);
        }
    }
    __syncthreads();
    if (tid < E) {
        atomicAdd(&g_gsum[tid], scol[tid]);
        if (scnt[tid]) atomicAdd(&g_cnt[tid], scnt[tid]);
    }
}

// ---------------- per-expert capacity selection + scatter ----------------
// one CTA per expert. keep = top-CAP assigned tokens by (noise desc, s asc);
// slot = rank of s among kept. Writes combine + dispatch nonzeros.
__global__ __launch_bounds__(256) void select_scatter(float* __restrict__ p_comb,
                                                      float* __restrict__ p_disp) {
    __shared__ u64 keys[1024];
    __shared__ int scount;
    int e = blockIdx.x, tid = threadIdx.x;
    if (tid == 0) scount = 0;
    __syncthreads();
    for (int s = tid; s < S; s += 256) {
        if (g_tok_e[s] == e) {
            int p = atomicAdd(&scount, 1);
            if (p < 1024)
                keys[p] = ((u64)__float_as_uint(g_tok_noise[s]) << 32) | (u32)(S - 1 - s);
        }
    }
    __syncthreads();
    int cnt = min(scount, 1024);
    if (cnt > CAP) {
        for (int i = tid; i < 1024; i += 256)
            if (i >= cnt) keys[i] = 0ull;
        __syncthreads();
        // bitonic sort descending
        for (int k = 2; k <= 1024; k <<= 1) {
            for (int j = k >> 1; j > 0; j >>= 1) {
                for (int i = tid; i < 1024; i += 256) {
                    int ixj = i ^ j;
                    if (ixj > i) {
                        u64 a = keys[i], b = keys[ixj];
                        bool dir = ((i & k) == 0);  // descending segment
                        if ((a < b) == dir) { keys[i] = b; keys[ixj] = a; }
                    }
                }
                __syncthreads();
            }
        }
    }
    int K = min(cnt, CAP);
    if (tid < K) {
        int si = S - 1 - (int)(u32)(keys[tid] & 0xffffffffu);
        int c = 0;
        for (int q = 0; q < K; q++) {
            int sq = S - 1 - (int)(u32)(keys[q] & 0xffffffffu);
            c += (sq < si);
        }
        size_t base = ((size_t)si * E + e) * CAP + c;
        if (p_comb) p_comb[base] = g_tok_g[si];
        if (p_disp) p_disp[base] = 1.0f;
    }
}

// ---------------- l_aux + exp_counts ----------------
__global__ void finalize_k(float* __restrict__ p_laux, float* __restrict__ p_cnt) {
    __shared__ float red[64];
    int t = threadIdx.x;
    float v = (g_gsum[t] * (1.f / S)) * ((float)g_cnt[t] * (1.f / S)) * (float)E;
    red[t] = v;
    if (p_cnt) p_cnt[t] = (float)g_cnt[t];
    __syncthreads();
    for (int o = 32; o >= 1; o >>= 1) {
        if (t < o) red[t] += red[t + o];
        __syncthreads();
    }
    if (t == 0 && p_laux) p_laux[0] = red[0];
}

// ---------------- launch ----------------
extern "C" void kernel_launch(void* const* d_in, const int* in_sizes, int n_in,
                              void* d_out, int out_size) {
    const float* x = (const float*)d_in[0];
    const float* wg = (const float*)d_in[1];
    float* o = (float*)d_out;

    const long long SEC = (long long)S * E * CAP;  // 67108864
    long long osz = (long long)out_size;
    float *pl = nullptr, *pc = nullptr, *pd = nullptr, *pn = nullptr;
    if (osz == 1 + 2 * SEC + E)      { pl = o; pc = o + 1; pd = o + 1 + SEC; pn = o + 1 + 2 * SEC; }
    else if (osz == 2 * SEC + E)     { pc = o; pd = o + SEC; pn = o + 2 * SEC; }
    else if (osz == 1 + SEC + E)     { pl = o; pc = o + 1; pn = o + 1 + SEC; }
    else if (osz == SEC)             { pc = o; }
    else if (osz == 2 * SEC)         { pc = o; pd = o + SEC; }
    else if (osz == SEC + E)         { pc = o; pn = o + SEC; }
    else if (osz == 1 + SEC)         { pl = o; pc = o + 1; }
    else {  // fallback: assume full concatenation order, clamp to what fits
        pl = o;
        if (osz > 1 + SEC) pc = o + 1;
        if (osz >= 1 + 2 * SEC) pd = o + 1 + SEC;
        if (osz >= 1 + 2 * SEC + E) pn = o + 1 + 2 * SEC;
    }

    init_scratch<<<1, 64>>>();
    gate_gemm<<<S / 64, 128>>>(x, wg);
    zero_out_k<<<1184, 256>>>(o, osz);
    select_scatter<<<E, 256>>>(pc, pd);
    finalize_k<<<1, 64>>>(pl, pn);
}

// round 6
// speedup vs baseline: 1.0587x; 1.0587x over previous
#include <cuda_runtime.h>

// TopKGate: S=8192, D=2048, E=64, top-1, capacity=128.
// Outputs concatenated fp32: l_aux [1], combine [S,E,C], dispatch [S,E,C], exp_counts [E]

#define S 8192
#define DD 2048
#define E 64
#define CAP 128

typedef unsigned int u32;
typedef unsigned long long u64;

// ---------------- scratch ----------------
__device__ int   g_tok_e[S];
__device__ float g_tok_g[S];
__device__ float g_tok_noise[S];
__device__ float g_gsum[E];
__device__ int   g_cnt[E];

// ---------------- packed f32x2 FMA ----------------
__device__ __forceinline__ u64 ffma2(u64 a, u64 b, u64 c) {
    u64 d;
    asm("fma.rn.f32x2 %0, %1, %2, %3;" : "=l"(d) : "l"(a), "l"(b), "l"(c));
    return d;
}
__device__ __forceinline__ u64 pack2(float x, float y) {
    u64 d;
    asm("mov.b64 %0, {%1, %2};" : "=l"(d) : "f"(x), "f"(y));
    return d;
}
__device__ __forceinline__ float2 unpack2(u64 a) {
    float x, y;
    asm("mov.b64 {%0, %1}, %2;" : "=f"(x), "=f"(y) : "l"(a));
    return make_float2(x, y);
}

// ---------------- JAX threefry2x32, partitionable (verified exact in R3) ----------
__device__ __forceinline__ u32 rotl32(u32 x, int r) { return (x << r) | (x >> (32 - r)); }

__device__ float jax_uniform_noise(u32 idx) {
    u32 x0 = 0u, x1 = idx;
    const u32 k0 = 0u, k1 = 42u, k2 = k0 ^ k1 ^ 0x1BD11BDAu;
    x0 += k0; x1 += k1;
#define RND(r) { x0 += x1; x1 = rotl32(x1, r); x1 ^= x0; }
    RND(13) RND(15) RND(26) RND(6)   x0 += k1; x1 += k2 + 1u;
    RND(17) RND(29) RND(16) RND(24)  x0 += k2; x1 += k0 + 2u;
    RND(13) RND(15) RND(26) RND(6)   x0 += k0; x1 += k1 + 3u;
    RND(17) RND(29) RND(16) RND(24)  x0 += k1; x1 += k2 + 4u;
    RND(13) RND(15) RND(26) RND(6)   x0 += k2; x1 += k0 + 5u;
#undef RND
    u32 bits = x0 ^ x1;
    float u = __uint_as_float((bits >> 9) | 0x3f800000u) - 1.0f;
    return u < 0.f ? 0.f : u;
}

// ---------------- init scratch ----------------
__global__ void init_scratch() {
    int t = threadIdx.x;
    if (t < E) { g_gsum[t] = 0.f; g_cnt[t] = 0; }
}

// ---------------- fused GEMM + softmax/argmax/noise + output zero-fill ----------------
// grid 128 CTAs x 128 threads. Zero-fill of d_out is interleaved per k-chunk so the
// DRAM writes hide under the FMA-bound mainloop (write BW was idle here before).
__global__ __launch_bounds__(128) void gate_gemm(const float* __restrict__ x,
                                                 const float* __restrict__ wg,
                                                 float* __restrict__ zout,
                                                 long long nz) {
    __shared__ float xs[64 * 68];
    __shared__ float ws[64 * 68];
    __shared__ float scol[E];
    __shared__ int scnt[E];

    int tid = threadIdx.x;
    int tok0 = blockIdx.x * 64;
    if (tid < E) { scol[tid] = 0.f; scnt[tid] = 0; }
    int ty = tid >> 3, tx = tid & 7;

    // zero-fill bookkeeping: float4 index space, 16384 threads, 256KB per step
    int n4 = (int)(nz >> 2);
    int total_steps = (n4 + 16383) >> 14;
    const int NCHUNK = DD / 64;  // 32
    int spc = (total_steps + NCHUNK - 1) / NCHUNK;  // steps per chunk (64 for full out)
    int zbase = blockIdx.x * 128 + tid;
    const float4 z4 = make_float4(0.f, 0.f, 0.f, 0.f);

    u64 acc[4][8];
#pragma unroll
    for (int i = 0; i < 4; i++)
#pragma unroll
        for (int jj = 0; jj < 8; jj++) acc[i][jj] = 0ull;

    float4 sx[8], sw[8];
#pragma unroll
    for (int u = 0; u < 8; u++) {
        int v = tid + u * 128; int r = v >> 4, c4 = v & 15;
        sx[u] = *(const float4*)&x[(size_t)(tok0 + r) * DD + c4 * 4];
        sw[u] = *(const float4*)&wg[(size_t)r * DD + c4 * 4];
    }

    for (int c = 0; c < NCHUNK; c++) {
#pragma unroll
        for (int u = 0; u < 8; u++) {
            int v = tid + u * 128; int r = v >> 4, c4 = v & 15;
            *(float4*)&xs[r * 68 + c4 * 4] = sx[u];
            *(float4*)&ws[r * 68 + c4 * 4] = sw[u];
        }
        __syncthreads();
        if (c + 1 < NCHUNK) {
            int k0 = (c + 1) * 64;
#pragma unroll
            for (int u = 0; u < 8; u++) {
                int v = tid + u * 128; int r = v >> 4, c4 = v & 15;
                sx[u] = *(const float4*)&x[(size_t)(tok0 + r) * DD + k0 + c4 * 4];
                sw[u] = *(const float4*)&wg[(size_t)r * DD + k0 + c4 * 4];
            }
        }
        // zero-fill slab for this chunk (no deps; hides under FMA issue shadow)
        {
            int st0 = c * spc;
            int st1 = st0 + spc;
            if (st1 > total_steps) st1 = total_steps;
            for (int st = st0; st < st1; st++) {
                int g = st * 16384 + zbase;
                if (g < n4) ((float4*)zout)[g] = z4;
            }
        }
        // compute 64 k-steps
#pragma unroll
        for (int kk = 0; kk < 64; kk += 4) {
            u64 xp0[4], xp1[4];
#pragma unroll
            for (int i = 0; i < 4; i++) {
                float4 xv = *(const float4*)&xs[(ty + 16 * i) * 68 + kk];
                xp0[i] = pack2(xv.x, xv.y);
                xp1[i] = pack2(xv.z, xv.w);
            }
#pragma unroll
            for (int jj = 0; jj < 8; jj++) {
                float4 wv = *(const float4*)&ws[(tx + 8 * jj) * 68 + kk];
                u64 w0 = pack2(wv.x, wv.y), w1 = pack2(wv.z, wv.w);
#pragma unroll
                for (int i = 0; i < 4; i++) {
                    acc[i][jj] = ffma2(xp0[i], w0, acc[i][jj]);
                    acc[i][jj] = ffma2(xp1[i], w1, acc[i][jj]);
                }
            }
        }
        __syncthreads();
    }

    // scalar tail of zero-fill (<= 3 floats)
    if (blockIdx.x == 0 && tid == 0) {
        for (long long v = (long long)n4 * 4; v < nz; v++) zout[v] = 0.f;
    }

    float vals[4][8];
#pragma unroll
    for (int i = 0; i < 4; i++)
#pragma unroll
        for (int jj = 0; jj < 8; jj++) {
            float2 f = unpack2(acc[i][jj]);
            vals[i][jj] = f.x + f.y;
        }

#pragma unroll
    for (int i = 0; i < 4; i++) {
        int t = ty + 16 * i;
        float m = -1e30f; int be = 0;
#pragma unroll
        for (int jj = 0; jj < 8; jj++) {
            float v = vals[i][jj]; int e = tx + 8 * jj;
            if (v > m) { m = v; be = e; }
        }
#pragma unroll
        for (int o = 4; o >= 1; o >>= 1) {
            float mo = __shfl_xor_sync(0xffffffffu, m, o);
            int eo = __shfl_xor_sync(0xffffffffu, be, o);
            if (mo > m || (mo == m && eo < be)) { m = mo; be = eo; }
        }
        float ex[8];
        float lsum = 0.f;
#pragma unroll
        for (int jj = 0; jj < 8; jj++) { ex[jj] = expf(vals[i][jj] - m); lsum += ex[jj]; }
#pragma unroll
        for (int o = 4; o >= 1; o >>= 1) lsum += __shfl_xor_sync(0xffffffffu, lsum, o);
        float inv = 1.0f / lsum;
#pragma unroll
        for (int jj = 0; jj < 8; jj++) atomicAdd(&scol[tx + 8 * jj], ex[jj] * inv);
        if (tx == 0) {
            int s = tok0 + t;
            g_tok_e[s] = be;
            g_tok_g[s] = inv;
            g_tok_noise[s] = jax_uniform_noise((u32)s * E + (u32)be);
            atomicAdd(&scnt[be], 1);
        }
    }
    __syncthreads();
    if (tid < E) {
        atomicAdd(&g_gsum[tid], scol[tid]);
        if (scnt[tid]) atomicAdd(&g_cnt[tid], scnt[tid]);
    }
}

// ---------------- per-expert selection (rank-based, no sort) + scatter + finalize ----
__global__ __launch_bounds__(256) void select_scatter(float* __restrict__ p_comb,
                                                      float* __restrict__ p_disp,
                                                      float* __restrict__ p_laux,
                                                      float* __restrict__ p_cnt) {
    __shared__ u64 keys[1024];
    __shared__ u32 kept[1024];
    __shared__ int scount;
    __shared__ float red[64];
    int e = blockIdx.x, tid = threadIdx.x;
    if (tid == 0) scount = 0;
    __syncthreads();
    for (int s = tid; s < S; s += 256) {
        if (g_tok_e[s] == e) {
            int p = atomicAdd(&scount, 1);
            if (p < 1024)
                keys[p] = ((u64)__float_as_uint(g_tok_noise[s]) << 32) | (u32)(S - 1 - s);
        }
    }
    __syncthreads();
    int cnt = min(scount, 1024);
    // pass 1: kept[i] = rank(key_i among keys, desc) < CAP
    for (int i = tid; i < cnt; i += 256) {
        u64 ki = keys[i];
        int r = 0;
        for (int j = 0; j < cnt; j++) r += (keys[j] > ki);
        kept[i] = (r < CAP) ? 1u : 0u;
    }
    __syncthreads();
    // pass 2: slot = #{kept j with s_j < s_i} ; (s_j < s_i) <=> low32(key_j) > low32(key_i)
    for (int i = tid; i < cnt; i += 256) {
        if (!kept[i]) continue;
        u32 li = (u32)keys[i];
        int slot = 0;
        for (int j = 0; j < cnt; j++) slot += (kept[j] & ((u32)keys[j] > li));
        int si = S - 1 - (int)li;
        size_t base = ((size_t)si * E + e) * CAP + slot;
        if (p_comb) p_comb[base] = g_tok_g[si];
        if (p_disp) p_disp[base] = 1.0f;
    }
    // finalize (folded): CTA 0 writes l_aux + exp_counts
    if (e == 0) {
        __syncthreads();
        if (tid < 64) {
            float v = (g_gsum[tid] * (1.f / S)) * ((float)g_cnt[tid] * (1.f / S)) * (float)E;
            red[tid] = v;
            if (p_cnt) p_cnt[tid] = (float)g_cnt[tid];
        }
        __syncthreads();
        if (tid < 32) {
            float v = red[tid] + red[tid + 32];
#pragma unroll
            for (int o = 16; o >= 1; o >>= 1) v += __shfl_xor_sync(0xffffffffu, v, o);
            if (tid == 0 && p_laux) p_laux[0] = v;
        }
    }
}

// ---------------- launch ----------------
extern "C" void kernel_launch(void* const* d_in, const int* in_sizes, int n_in,
                              void* d_out, int out_size) {
    const float* x = (const float*)d_in[0];
    const float* wg = (const float*)d_in[1];
    float* o = (float*)d_out;

    const long long SEC = (long long)S * E * CAP;  // 67108864
    long long osz = (long long)out_size;
    float *pl = nullptr, *pc = nullptr, *pd = nullptr, *pn = nullptr;
    if (osz == 1 + 2 * SEC + E)      { pl = o; pc = o + 1; pd = o + 1 + SEC; pn = o + 1 + 2 * SEC; }
    else if (osz == 2 * SEC + E)     { pc = o; pd = o + SEC; pn = o + 2 * SEC; }
    else if (osz == 1 + SEC + E)     { pl = o; pc = o + 1; pn = o + 1 + SEC; }
    else if (osz == SEC)             { pc = o; }
    else if (osz == 2 * SEC)         { pc = o; pd = o + SEC; }
    else if (osz == SEC + E)         { pc = o; pn = o + SEC; }
    else if (osz == 1 + SEC)         { pl = o; pc = o + 1; }
    else {
        pl = o;
        if (osz > 1 + SEC) pc = o + 1;
        if (osz >= 1 + 2 * SEC) pd = o + 1 + SEC;
        if (osz >= 1 + 2 * SEC + E) pn = o + 1 + 2 * SEC;
    }

    init_scratch<<<1, 64>>>();
    gate_gemm<<<S / 64, 128>>>(x, wg, o, osz);
    select_scatter<<<E, 256>>>(pc, pd, pl, pn);
}

// round 8
// speedup vs baseline: 1.4086x; 1.3306x over previous
#include <cuda_runtime.h>

// TopKGate: S=8192, D=2048, E=64, top-1, capacity=128. Single fused kernel.
// Outputs concatenated fp32: l_aux [1], combine [S,E,C], dispatch [S,E,C], exp_counts [E]

#define S 8192
#define DD 2048
#define E 64
#define CAP 128
#define NCTA 128

typedef unsigned int u32;
typedef unsigned long long u64;

// ---------------- scratch ----------------
__device__ int   g_tok_e[S];
__device__ float g_tok_g[S];
__device__ float g_tok_noise[S];
__device__ float g_part_gsum[NCTA][E];
__device__ int   g_part_cnt[NCTA][E];
__device__ int   g_count = 0;   // grid barrier arrivals (self-resetting)
__device__ u32   g_sense = 0;   // grid barrier sense (monotonic across replays)

// ---------------- packed f32x2 FMA ----------------
__device__ __forceinline__ u64 ffma2(u64 a, u64 b, u64 c) {
    u64 d;
    asm("fma.rn.f32x2 %0, %1, %2, %3;" : "=l"(d) : "l"(a), "l"(b), "l"(c));
    return d;
}
__device__ __forceinline__ u64 pack2(float x, float y) {
    u64 d;
    asm("mov.b64 %0, {%1, %2};" : "=l"(d) : "f"(x), "f"(y));
    return d;
}
__device__ __forceinline__ float2 unpack2(u64 a) {
    float x, y;
    asm("mov.b64 {%0, %1}, %2;" : "=f"(x), "=f"(y) : "l"(a));
    return make_float2(x, y);
}

// ---------------- JAX threefry2x32, partitionable (verified exact) ----------
__device__ __forceinline__ u32 rotl32(u32 x, int r) { return (x << r) | (x >> (32 - r)); }

__device__ float jax_uniform_noise(u32 idx) {
    u32 x0 = 0u, x1 = idx;
    const u32 k0 = 0u, k1 = 42u, k2 = k0 ^ k1 ^ 0x1BD11BDAu;
    x0 += k0; x1 += k1;
#define RND(r) { x0 += x1; x1 = rotl32(x1, r); x1 ^= x0; }
    RND(13) RND(15) RND(26) RND(6)   x0 += k1; x1 += k2 + 1u;
    RND(17) RND(29) RND(16) RND(24)  x0 += k2; x1 += k0 + 2u;
    RND(13) RND(15) RND(26) RND(6)   x0 += k0; x1 += k1 + 3u;
    RND(17) RND(29) RND(16) RND(24)  x0 += k1; x1 += k2 + 4u;
    RND(13) RND(15) RND(26) RND(6)   x0 += k2; x1 += k0 + 5u;
#undef RND
    u32 bits = x0 ^ x1;
    float u = __uint_as_float((bits >> 9) | 0x3f800000u) - 1.0f;
    return u < 0.f ? 0.f : u;
}

// ================= fused kernel =================
// 128 CTAs x 256 threads, guaranteed single wave (<=148 SMs, 35KB smem, 1 CTA/SM ok).
// Warps 0-3: 64x64 GEMM tile + softmax/argmax/noise.  Warps 4-7: zero-fill d_out.
// Grid barrier, then CTAs 0-63 do per-expert capacity selection; CTA0 finalizes.
__global__ __launch_bounds__(256, 1) void topk_fused(const float* __restrict__ x,
                                                     const float* __restrict__ wg,
                                                     float* __restrict__ zout,
                                                     long long nz,
                                                     float* __restrict__ p_comb,
                                                     float* __restrict__ p_disp,
                                                     float* __restrict__ p_laux,
                                                     float* __restrict__ p_cnt) {
    __shared__ float xs[64 * 68];
    __shared__ float ws[64 * 68];
    __shared__ float scol[E];
    __shared__ int scnt[E];
    __shared__ int ssel;

    int tid = threadIdx.x;
    int bid = blockIdx.x;
    int tok0 = bid * 64;
    const int NCHUNK = DD / 64;  // 32

    if (tid < E) { scol[tid] = 0.f; scnt[tid] = 0; }
    __syncthreads();

    if (tid < 128) {
        // ---------------- compute path (warps 0-3) ----------------
        int ty = tid >> 3, tx = tid & 7;
        u64 acc[4][8];
#pragma unroll
        for (int i = 0; i < 4; i++)
#pragma unroll
            for (int jj = 0; jj < 8; jj++) acc[i][jj] = 0ull;

        float4 sx[8], sw[8];
#pragma unroll
        for (int u = 0; u < 8; u++) {
            int v = tid + u * 128; int r = v >> 4, c4 = v & 15;
            sx[u] = *(const float4*)&x[(size_t)(tok0 + r) * DD + c4 * 4];
            sw[u] = *(const float4*)&wg[(size_t)r * DD + c4 * 4];
        }

        for (int c = 0; c < NCHUNK; c++) {
#pragma unroll
            for (int u = 0; u < 8; u++) {
                int v = tid + u * 128; int r = v >> 4, c4 = v & 15;
                *(float4*)&xs[r * 68 + c4 * 4] = sx[u];
                *(float4*)&ws[r * 68 + c4 * 4] = sw[u];
            }
            __syncthreads();
            if (c + 1 < NCHUNK) {
                int k0 = (c + 1) * 64;
#pragma unroll
                for (int u = 0; u < 8; u++) {
                    int v = tid + u * 128; int r = v >> 4, c4 = v & 15;
                    sx[u] = *(const float4*)&x[(size_t)(tok0 + r) * DD + k0 + c4 * 4];
                    sw[u] = *(const float4*)&wg[(size_t)r * DD + k0 + c4 * 4];
                }
            }
#pragma unroll
            for (int kk = 0; kk < 64; kk += 4) {
                u64 xp0[4], xp1[4];
#pragma unroll
                for (int i = 0; i < 4; i++) {
                    float4 xv = *(const float4*)&xs[(ty + 16 * i) * 68 + kk];
                    xp0[i] = pack2(xv.x, xv.y);
                    xp1[i] = pack2(xv.z, xv.w);
                }
#pragma unroll
                for (int jj = 0; jj < 8; jj++) {
                    float4 wv = *(const float4*)&ws[(tx + 8 * jj) * 68 + kk];
                    u64 w0 = pack2(wv.x, wv.y), w1 = pack2(wv.z, wv.w);
#pragma unroll
                    for (int i = 0; i < 4; i++) {
                        acc[i][jj] = ffma2(xp0[i], w0, acc[i][jj]);
                        acc[i][jj] = ffma2(xp1[i], w1, acc[i][jj]);
                    }
                }
            }
            __syncthreads();
        }

        float vals[4][8];
#pragma unroll
        for (int i = 0; i < 4; i++)
#pragma unroll
            for (int jj = 0; jj < 8; jj++) {
                float2 f = unpack2(acc[i][jj]);
                vals[i][jj] = f.x + f.y;
            }

#pragma unroll
        for (int i = 0; i < 4; i++) {
            int t = ty + 16 * i;
            float m = -1e30f; int be = 0;
#pragma unroll
            for (int jj = 0; jj < 8; jj++) {
                float v = vals[i][jj]; int e = tx + 8 * jj;
                if (v > m) { m = v; be = e; }
            }
#pragma unroll
            for (int o = 4; o >= 1; o >>= 1) {
                float mo = __shfl_xor_sync(0xffffffffu, m, o);
                int eo = __shfl_xor_sync(0xffffffffu, be, o);
                if (mo > m || (mo == m && eo < be)) { m = mo; be = eo; }
            }
            float ex[8];
            float lsum = 0.f;
#pragma unroll
            for (int jj = 0; jj < 8; jj++) { ex[jj] = expf(vals[i][jj] - m); lsum += ex[jj]; }
#pragma unroll
            for (int o = 4; o >= 1; o >>= 1) lsum += __shfl_xor_sync(0xffffffffu, lsum, o);
            float inv = 1.0f / lsum;
#pragma unroll
            for (int jj = 0; jj < 8; jj++) atomicAdd(&scol[tx + 8 * jj], ex[jj] * inv);
            if (tx == 0) {
                int s = tok0 + t;
                g_tok_e[s] = be;
                g_tok_g[s] = inv;
                g_tok_noise[s] = jax_uniform_noise((u32)s * E + (u32)be);
                atomicAdd(&scnt[be], 1);
            }
        }
    } else {
        // ---------------- store path (warps 4-7): zero-fill d_out ----------------
        int zt = (bid << 7) + (tid - 128);            // 0..16383
        int n4 = (int)(nz >> 2);
        int total = (n4 + 16383) >> 14;
        int spc = (total + NCHUNK - 1) / NCHUNK;
        const float4 z4 = make_float4(0.f, 0.f, 0.f, 0.f);
        for (int c = 0; c < NCHUNK; c++) {
            int st0 = c * spc;
            int st1 = st0 + spc; if (st1 > total) st1 = total;
            for (int st = st0; st < st1; st++) {
                int g = st * 16384 + zt;
                if (g < n4) ((float4*)zout)[g] = z4;
            }
            __syncthreads();
            __syncthreads();
        }
        if (bid == 0 && tid == 128) {
            for (long long v = (nz >> 2) << 2; v < nz; v++) zout[v] = 0.f;
        }
    }

    __syncthreads();
    // per-CTA partials (no global pre-zero needed)
    if (tid < E) {
        g_part_gsum[bid][tid] = scol[tid];
        g_part_cnt[bid][tid] = scnt[tid];
    }
    __syncthreads();

    // ---------------- device-wide sense-reversing barrier ----------------
    if (tid == 0) {
        volatile u32* vs = &g_sense;
        u32 s0 = *vs;
        __threadfence();
        int old = atomicAdd(&g_count, 1);
        if (old == NCTA - 1) {
            g_count = 0;
            __threadfence();
            atomicAdd(&g_sense, 1u);
        }
        while (*vs == s0) {}
        __threadfence();
    }
    __syncthreads();

    // ---------------- phase B: per-expert selection (CTAs 0-63) ----------------
    if (bid >= E) return;
    int e = bid;
    u64* keys = (u64*)xs;   // 8KB reuse
    u32* kept = (u32*)ws;   // 4KB reuse
    if (tid == 0) ssel = 0;
    __syncthreads();
    for (int s = tid; s < S; s += 256) {
        if (g_tok_e[s] == e) {
            int p = atomicAdd(&ssel, 1);
            if (p < 1024)
                keys[p] = ((u64)__float_as_uint(g_tok_noise[s]) << 32) | (u32)(S - 1 - s);
        }
    }
    __syncthreads();
    int cnt = min(ssel, 1024);
    for (int i = tid; i < cnt; i += 256) {
        u64 ki = keys[i];
        int r = 0;
        for (int j = 0; j < cnt; j++) r += (keys[j] > ki);
        kept[i] = (r < CAP) ? 1u : 0u;
    }
    __syncthreads();
    for (int i = tid; i < cnt; i += 256) {
        if (!kept[i]) continue;
        u32 li = (u32)keys[i];
        int slot = 0;
        for (int j = 0; j < cnt; j++) slot += (kept[j] & ((u32)keys[j] > li));
        int si = S - 1 - (int)li;
        size_t base = ((size_t)si * E + e) * CAP + slot;
        if (p_comb) p_comb[base] = g_tok_g[si];
        if (p_disp) p_disp[base] = 1.0f;
    }

    // ---------------- finalize: l_aux + exp_counts (CTA 0) ----------------
    if (bid == 0) {
        __syncthreads();
        if (tid < E) {
            float gs = 0.f; int cc = 0;
            for (int k = 0; k < NCTA; k++) { gs += g_part_gsum[k][tid]; cc += g_part_cnt[k][tid]; }
            if (p_cnt) p_cnt[tid] = (float)cc;
            scol[tid] = (gs * (1.f / S)) * ((float)cc * (1.f / S)) * (float)E;
        }
        __syncthreads();
        if (tid < 32) {
            float v = scol[tid] + scol[tid + 32];
#pragma unroll
            for (int o = 16; o >= 1; o >>= 1) v += __shfl_xor_sync(0xffffffffu, v, o);
            if (tid == 0 && p_laux) p_laux[0] = v;
        }
    }
}

// ---------------- launch ----------------
extern "C" void kernel_launch(void* const* d_in, const int* in_sizes, int n_in,
                              void* d_out, int out_size) {
    const float* x = (const float*)d_in[0];
    const float* wg = (const float*)d_in[1];
    float* o = (float*)d_out;

    const long long SEC = (long long)S * E * CAP;  // 67108864
    long long osz = (long long)out_size;
    float *pl = nullptr, *pc = nullptr, *pd = nullptr, *pn = nullptr;
    if (osz == 1 + 2 * SEC + E)      { pl = o; pc = o + 1; pd = o + 1 + SEC; pn = o + 1 + 2 * SEC; }
    else if (osz == 2 * SEC + E)     { pc = o; pd = o + SEC; pn = o + 2 * SEC; }
    else if (osz == 1 + SEC + E)     { pl = o; pc = o + 1; pn = o + 1 + SEC; }
    else if (osz == SEC)             { pc = o; }
    else if (osz == 2 * SEC)         { pc = o; pd = o + SEC; }
    else if (osz == SEC + E)         { pc = o; pn = o + SEC; }
    else if (osz == 1 + SEC)         { pl = o; pc = o + 1; }
    else {
        pl = o;
        if (osz > 1 + SEC) pc = o + 1;
        if (osz >= 1 + 2 * SEC) pd = o + 1 + SEC;
        if (osz >= 1 + 2 * SEC + E) pn = o + 1 + 2 * SEC;
    }

    topk_fused<<<NCTA, 256>>>(x, wg, o, osz, pc, pd, pl, pn);
}